// round 5
// baseline (speedup 1.0000x reference)
#include <cuda_runtime.h>
#include <cuda_bf16.h>
#include <math.h>

#define SEQ   4096
#define DIM   512
#define KCONV 3
#define KTOT  (DIM * KCONV)      // 1536
#define MAXOUT (4 * SEQ)         // 16384
#define LN_EPS 1e-5f

// -------- scratch (no allocations allowed) --------
__device__ float g_Bt1[KTOT * DIM];   // conv1 weights as [K=1536][N=512]
__device__ float g_Bt2[KTOT * DIM];   // conv2 weights as [K=1536][N=512]
__device__ float g_y1[SEQ * DIM];     // conv1 output (pre-LN)
__device__ float g_x1[SEQ * DIM];     // LN1+ReLU output
__device__ float g_y2[SEQ * DIM];     // conv2 output (pre-LN)
__device__ int   g_dur[SEQ];
__device__ int   g_cum[SEQ];

// ============================================================
// Weight permute: w[o][d][k] -> Bt[k*512+d][o]
// ============================================================
__global__ void wtrans_kernel(const float* __restrict__ w1,
                              const float* __restrict__ w2) {
    int idx = blockIdx.x * 256 + threadIdx.x;       // 0 .. 786431
    const float* w = blockIdx.y ? w2 : w1;
    float* Bt      = blockIdx.y ? g_Bt2 : g_Bt1;
    int o = idx & 511;
    int c = idx >> 9;          // 0..1535
    int k = c >> 9;            // 0..2
    int d = c & 511;
    Bt[idx] = w[o * KTOT + d * KCONV + k];
}

// ============================================================
// Conv-as-GEMM: dst[s][o] = sum_c A[s][c] * Bt[c][o] + bias[o]
// A[s][k*512+d] = src[s+k-1][d] (zero padded), implicit im2col.
// BM=128, BN=64, BK=16, 128 threads, 8x8 microtile,
// double-buffered smem + register prefetch. grid = 32 x 8 = 256.
// ============================================================
template <int PASS>
__global__ __launch_bounds__(128, 4)
void conv_gemm_kernel(const float* __restrict__ enc,
                      const float* __restrict__ bias) {
    const float* src = (PASS == 0) ? enc : g_x1;
    const float* Bt  = (PASS == 0) ? g_Bt1 : g_Bt2;
    float* dst       = (PASS == 0) ? g_y1 : g_y2;

    __shared__ float As[2][16][128];   // [buf][k][m]  16KB
    __shared__ float Bs[2][16][64];    // [buf][k][n]   8KB

    const int bm = blockIdx.x * 128;
    const int bn = blockIdx.y * 64;
    const int tid = threadIdx.x;
    const int tx = tid & 7;         // n-dim: 8 cols each -> 64
    const int ty = tid >> 3;        // m-dim: 8 rows each -> 128

    // B global load mapping (2 float4 per thread)
    const int kkB0 = tid >> 4;            // 0..7
    const int nB0  = (tid & 15) * 4;      // 0..60
    const int kkB1 = kkB0 + 8;            // 8..15

    float acc[8][8];
#pragma unroll
    for (int i = 0; i < 8; i++)
#pragma unroll
        for (int j = 0; j < 8; j++) acc[i][j] = 0.f;

    const int NK = KTOT / 16;   // 96

    // ---- prologue: tile 0 -> buf 0  (kseg=0, dbase=0)
    {
        int srow = bm + tid - 1;
        float4 a[4];
#pragma unroll
        for (int j = 0; j < 4; j++) a[j] = make_float4(0.f, 0.f, 0.f, 0.f);
        if (srow >= 0 && srow < SEQ) {
#pragma unroll
            for (int j = 0; j < 4; j++)
                a[j] = *(const float4*)&src[srow * DIM + j * 4];
        }
#pragma unroll
        for (int j = 0; j < 4; j++) {
            As[0][j * 4 + 0][tid] = a[j].x;
            As[0][j * 4 + 1][tid] = a[j].y;
            As[0][j * 4 + 2][tid] = a[j].z;
            As[0][j * 4 + 3][tid] = a[j].w;
        }
        *(float4*)&Bs[0][kkB0][nB0] = *(const float4*)&Bt[kkB0 * DIM + bn + nB0];
        *(float4*)&Bs[0][kkB1][nB0] = *(const float4*)&Bt[kkB1 * DIM + bn + nB0];
    }
    __syncthreads();

    int buf = 0;
#pragma unroll 1
    for (int t = 0; t < NK; ++t) {
        const int tn = t + 1;
        float4 pa[4], pb0, pb1;
        if (tn < NK) {
            const int k0 = tn * 16;
            const int kseg  = k0 >> 9;
            const int dbase = k0 & 511;
            int srow = bm + tid + kseg - 1;
#pragma unroll
            for (int j = 0; j < 4; j++) pa[j] = make_float4(0.f, 0.f, 0.f, 0.f);
            if (srow >= 0 && srow < SEQ) {
#pragma unroll
                for (int j = 0; j < 4; j++)
                    pa[j] = *(const float4*)&src[srow * DIM + dbase + j * 4];
            }
            pb0 = *(const float4*)&Bt[(k0 + kkB0) * DIM + bn + nB0];
            pb1 = *(const float4*)&Bt[(k0 + kkB1) * DIM + bn + nB0];
        }

        // ---- compute on current buffer
#pragma unroll
        for (int kk = 0; kk < 16; kk++) {
            float4 x0 = *(const float4*)&As[buf][kk][ty * 8];
            float4 x1 = *(const float4*)&As[buf][kk][ty * 8 + 4];
            float4 y0 = *(const float4*)&Bs[buf][kk][tx * 8];
            float4 y1 = *(const float4*)&Bs[buf][kk][tx * 8 + 4];
            float a[8] = {x0.x, x0.y, x0.z, x0.w, x1.x, x1.y, x1.z, x1.w};
            float b[8] = {y0.x, y0.y, y0.z, y0.w, y1.x, y1.y, y1.z, y1.w};
#pragma unroll
            for (int i = 0; i < 8; i++)
#pragma unroll
                for (int j = 0; j < 8; j++)
                    acc[i][j] = fmaf(a[i], b[j], acc[i][j]);
        }

        if (tn < NK) {
            const int nb = buf ^ 1;
#pragma unroll
            for (int j = 0; j < 4; j++) {
                As[nb][j * 4 + 0][tid] = pa[j].x;
                As[nb][j * 4 + 1][tid] = pa[j].y;
                As[nb][j * 4 + 2][tid] = pa[j].z;
                As[nb][j * 4 + 3][tid] = pa[j].w;
            }
            *(float4*)&Bs[nb][kkB0][nB0] = pb0;
            *(float4*)&Bs[nb][kkB1][nB0] = pb1;
            __syncthreads();
            buf = nb;
        }
    }

    // ---- epilogue
    float4 bb0 = *(const float4*)&bias[bn + tx * 8];
    float4 bb1 = *(const float4*)&bias[bn + tx * 8 + 4];
#pragma unroll
    for (int i = 0; i < 8; i++) {
        int row = bm + ty * 8 + i;
        float4 o0, o1;
        o0.x = acc[i][0] + bb0.x; o0.y = acc[i][1] + bb0.y;
        o0.z = acc[i][2] + bb0.z; o0.w = acc[i][3] + bb0.w;
        o1.x = acc[i][4] + bb1.x; o1.y = acc[i][5] + bb1.y;
        o1.z = acc[i][6] + bb1.z; o1.w = acc[i][7] + bb1.w;
        *(float4*)&dst[row * DIM + bn + tx * 8]     = o0;
        *(float4*)&dst[row * DIM + bn + tx * 8 + 4] = o1;
    }
}

// ------------- block reduction helper (128 threads) -------------
__device__ __forceinline__ void reduce2_128(float& s, float& q, float* sh) {
#pragma unroll
    for (int off = 16; off; off >>= 1) {
        s += __shfl_down_sync(0xFFFFFFFFu, s, off);
        q += __shfl_down_sync(0xFFFFFFFFu, q, off);
    }
    int w = threadIdx.x >> 5;
    if ((threadIdx.x & 31) == 0) { sh[w] = s; sh[4 + w] = q; }
    __syncthreads();
    s = sh[0] + sh[1] + sh[2] + sh[3];
    q = sh[4] + sh[5] + sh[6] + sh[7];
}

// ============================================================
// LN1 + ReLU: g_y1 -> g_x1.  128 threads/row, float4.
// ============================================================
__global__ __launch_bounds__(128)
void ln_relu_kernel(const float* __restrict__ g,
                    const float* __restrict__ b) {
    __shared__ float sh[8];
    int row = blockIdx.x;
    int tid = threadIdx.x;
    float4 v = ((const float4*)(g_y1 + row * DIM))[tid];
    float s = v.x + v.y + v.z + v.w;
    float q = v.x * v.x + v.y * v.y + v.z * v.z + v.w * v.w;
    reduce2_128(s, q, sh);
    float mean = s * (1.f / DIM);
    float var  = q * (1.f / DIM) - mean * mean;
    float rstd = rsqrtf(var + LN_EPS);
    float4 gg = ((const float4*)g)[tid];
    float4 bb = ((const float4*)b)[tid];
    float4 o;
    o.x = fmaxf((v.x - mean) * rstd * gg.x + bb.x, 0.f);
    o.y = fmaxf((v.y - mean) * rstd * gg.y + bb.y, 0.f);
    o.z = fmaxf((v.z - mean) * rstd * gg.z + bb.z, 0.f);
    o.w = fmaxf((v.w - mean) * rstd * gg.w + bb.w, 0.f);
    ((float4*)(g_x1 + row * DIM))[tid] = o;
}

// ============================================================
// LN2 + ReLU + linear + duration: g_y2 -> g_dur (x2 never stored)
// ============================================================
__global__ __launch_bounds__(128)
void ln_dur_kernel(const float* __restrict__ g,
                   const float* __restrict__ b,
                   const float* __restrict__ lw,
                   const float* __restrict__ lb) {
    __shared__ float sh[8];
    int row = blockIdx.x;
    int tid = threadIdx.x;
    float4 v = ((const float4*)(g_y2 + row * DIM))[tid];
    float s = v.x + v.y + v.z + v.w;
    float q = v.x * v.x + v.y * v.y + v.z * v.z + v.w * v.w;
    reduce2_128(s, q, sh);
    float mean = s * (1.f / DIM);
    float var  = q * (1.f / DIM) - mean * mean;
    float rstd = rsqrtf(var + LN_EPS);
    float4 gg = ((const float4*)g)[tid];
    float4 bb = ((const float4*)b)[tid];
    float4 ww = ((const float4*)lw)[tid];
    float ox = fmaxf((v.x - mean) * rstd * gg.x + bb.x, 0.f);
    float oy = fmaxf((v.y - mean) * rstd * gg.y + bb.y, 0.f);
    float oz = fmaxf((v.z - mean) * rstd * gg.z + bb.z, 0.f);
    float ow = fmaxf((v.w - mean) * rstd * gg.w + bb.w, 0.f);
    float t = ox * ww.x + oy * ww.y + oz * ww.z + ow * ww.w;
    __syncthreads();   // protect sh reuse
    float dummy = 0.f;
    reduce2_128(t, dummy, sh);
    if (tid == 0) {
        float pred = fmaxf(t + lb[0], 0.f);
        g_dur[row] = (int)floorf(pred + 0.5f);
    }
}

// ============================================================
// Inclusive cumsum of g_dur (4096 ints), single block.
// ============================================================
__global__ __launch_bounds__(1024)
void cumsum_kernel() {
    __shared__ int part[1024];
    int tid = threadIdx.x;
    int v[4];
    int s = 0;
#pragma unroll
    for (int i = 0; i < 4; i++) { v[i] = g_dur[tid * 4 + i]; s += v[i]; }
    part[tid] = s;
    __syncthreads();
    for (int off = 1; off < 1024; off <<= 1) {
        int t = 0;
        if (tid >= off) t = part[tid - off];
        __syncthreads();
        if (tid >= off) part[tid] += t;
        __syncthreads();
    }
    int run = (tid > 0) ? part[tid - 1] : 0;
#pragma unroll
    for (int i = 0; i < 4; i++) { run += v[i]; g_cum[tid * 4 + i] = run; }
}

// ============================================================
// Length regulation: one block per output frame t.
// ============================================================
__global__ __launch_bounds__(128)
void gather_kernel(const float* __restrict__ enc,
                   float* __restrict__ out,
                   float* __restrict__ pos,
                   int write_pos) {
    int t = blockIdx.x;
    int tid = threadIdx.x;
    int total = g_cum[SEQ - 1];
    float4 val = make_float4(0.f, 0.f, 0.f, 0.f);
    if (t < total) {
        int lo = 0, hi = SEQ;
        while (lo < hi) {
            int mid = (lo + hi) >> 1;
            if (g_cum[mid] <= t) lo = mid + 1; else hi = mid;
        }
        if (lo > SEQ - 1) lo = SEQ - 1;
        val = ((const float4*)(enc + lo * DIM))[tid];
    }
    ((float4*)(out + t * DIM))[tid] = val;
    if (write_pos && tid == 0) pos[t] = (float)(t + 1);
}

// ============================================================
extern "C" void kernel_launch(void* const* d_in, const int* in_sizes, int n_in,
                              void* d_out, int out_size) {
    const float* enc = (const float*)d_in[0];
    const float* c1w = (const float*)d_in[1];
    const float* c1b = (const float*)d_in[2];
    const float* g1  = (const float*)d_in[3];
    const float* b1  = (const float*)d_in[4];
    const float* c2w = (const float*)d_in[5];
    const float* c2b = (const float*)d_in[6];
    const float* g2  = (const float*)d_in[7];
    const float* b2  = (const float*)d_in[8];
    const float* lw  = (const float*)d_in[9];
    const float* lb  = (const float*)d_in[10];
    float* out = (float*)d_out;

    wtrans_kernel<<<dim3((KTOT * DIM) / 256, 2), 256>>>(c1w, c2w);
    conv_gemm_kernel<0><<<dim3(SEQ / 128, DIM / 64), 128>>>(enc, c1b);
    ln_relu_kernel<<<SEQ, 128>>>(g1, b1);
    conv_gemm_kernel<1><<<dim3(SEQ / 128, DIM / 64), 128>>>(enc, c2b);
    ln_dur_kernel<<<SEQ, 128>>>(g2, b2, lw, lb);
    cumsum_kernel<<<1, 1024>>>();

    int write_pos = (out_size >= MAXOUT * DIM + MAXOUT) ? 1 : 0;
    gather_kernel<<<MAXOUT, 128>>>(enc, out, out + (size_t)MAXOUT * DIM, write_pos);
}

// round 6
// speedup vs baseline: 1.3703x; 1.3703x over previous
#include <cuda_runtime.h>
#include <cuda_bf16.h>
#include <math.h>

#define SEQ   4096
#define DIM   512
#define KCONV 3
#define KTOT  (DIM * KCONV)      // 1536
#define MAXOUT (4 * SEQ)         // 16384
#define LN_EPS 1e-5f

// packed fp32x2 FMA (Blackwell FFMA2) — full fp32 precision per lane
#define FMA_F32X2(d, a, b, c) \
    asm("fma.rn.f32x2 %0, %1, %2, %3;" : "=l"(d) : "l"(a), "l"(b), "l"(c))
#define PACK2(d, lo, hi) \
    asm("mov.b64 %0, {%1, %2};" : "=l"(d) : "f"(lo), "f"(hi))
#define UNPACK2(lo, hi, v) \
    asm("mov.b64 {%0, %1}, %2;" : "=f"(lo), "=f"(hi) : "l"(v))

// -------- scratch (no allocations allowed) --------
__device__ float g_Bt1[KTOT * DIM];   // conv1 weights as [K=1536][N=512]
__device__ float g_Bt2[KTOT * DIM];   // conv2 weights as [K=1536][N=512]
__device__ float g_y1[SEQ * DIM];     // conv1 output (pre-LN)
__device__ float g_x1[SEQ * DIM];     // LN1+ReLU output
__device__ float g_y2[SEQ * DIM];     // conv2 output (pre-LN)
__device__ int   g_dur[SEQ];
__device__ int   g_cum[SEQ];

// ============================================================
// Weight permute: w[o][d][k] -> Bt[k*512+d][o]
// ============================================================
__global__ void wtrans_kernel(const float* __restrict__ w1,
                              const float* __restrict__ w2) {
    int idx = blockIdx.x * 256 + threadIdx.x;       // 0 .. 786431
    const float* w = blockIdx.y ? w2 : w1;
    float* Bt      = blockIdx.y ? g_Bt2 : g_Bt1;
    int o = idx & 511;
    int c = idx >> 9;          // 0..1535
    int k = c >> 9;            // 0..2
    int d = c & 511;
    Bt[idx] = w[o * KTOT + d * KCONV + k];
}

// ============================================================
// Conv-as-GEMM: dst[s][o] = sum_c A[s][c] * Bt[c][o] + bias[o]
// A[s][k*512+d] = src[s+k-1][d] (zero padded), implicit im2col.
// R1 config: BM=128, BN=64, BK=16, 256 threads, grid 32x8=256.
// Microtile 8(M) x 4(N) per thread, computed as 4 M-pairs in
// packed f32x2 (FFMA2): halves FFMA instruction count at full
// fp32 precision.
// ============================================================
template <int PASS>
__global__ __launch_bounds__(256, 2)
void conv_gemm_kernel(const float* __restrict__ enc,
                      const float* __restrict__ bias) {
    const float* src = (PASS == 0) ? enc : g_x1;
    const float* Bt  = (PASS == 0) ? g_Bt1 : g_Bt2;
    float* dst       = (PASS == 0) ? g_y1 : g_y2;

    __shared__ float As[16][132];   // [BK][BM+pad] ; pad keeps 16B alignment
    __shared__ float Bs[16][64];    // [BK][BN]

    const int bm = blockIdx.x * 128;
    const int bn = blockIdx.y * 64;
    const int tid = threadIdx.x;
    const int tx = tid & 15;        // 0..15 -> n (4 cols each)
    const int ty = tid >> 4;        // 0..15 -> m (8 rows each)

    // acc2[ip][j]: M-pair ip (rows 2ip, 2ip+1 of the 8), N col j
    unsigned long long acc2[4][4];
#pragma unroll
    for (int i = 0; i < 4; i++)
#pragma unroll
        for (int j = 0; j < 4; j++) acc2[i][j] = 0ull;

    for (int k0 = 0; k0 < KTOT; k0 += 16) {
        const int kseg  = k0 >> 9;       // constant across the BK tile
        const int dbase = k0 & 511;
        // load A tile (implicit shifted rows of src)
#pragma unroll
        for (int i = 0; i < 8; i++) {
            int e  = tid + i * 256;      // 0..2047
            int kk = e & 15;
            int r  = e >> 4;             // 0..127
            int srow = bm + r + kseg - 1;
            float v = 0.f;
            if (srow >= 0 && srow < SEQ) v = src[srow * DIM + dbase + kk];
            As[kk][r] = v;
        }
        // load B tile
#pragma unroll
        for (int i = 0; i < 4; i++) {
            int e  = tid + i * 256;      // 0..1023
            int kk = e >> 6;
            int n  = e & 63;
            Bs[kk][n] = Bt[(k0 + kk) * DIM + bn + n];
        }
        __syncthreads();

#pragma unroll
        for (int kk = 0; kk < 16; kk++) {
            // a: 8 M values as 4 aligned f32x2 pairs (LDS.128 into reg pairs)
            ulonglong2 a01 = *(const ulonglong2*)&As[kk][ty * 8];
            ulonglong2 a23 = *(const ulonglong2*)&As[kk][ty * 8 + 4];
            unsigned long long am[4] = {a01.x, a01.y, a23.x, a23.y};
            // b: 4 N values, broadcast each into both lanes
            float4 b4 = *(const float4*)&Bs[kk][tx * 4];
            unsigned long long bb[4];
            PACK2(bb[0], b4.x, b4.x);
            PACK2(bb[1], b4.y, b4.y);
            PACK2(bb[2], b4.z, b4.z);
            PACK2(bb[3], b4.w, b4.w);
#pragma unroll
            for (int i = 0; i < 4; i++)
#pragma unroll
                for (int j = 0; j < 4; j++)
                    FMA_F32X2(acc2[i][j], am[i], bb[j], acc2[i][j]);
        }
        __syncthreads();
    }

    // ---- epilogue: unpack pairs, add bias, store
    float4 bbv = *(const float4*)&bias[bn + tx * 4];
    float bj[4] = {bbv.x, bbv.y, bbv.z, bbv.w};
#pragma unroll
    for (int i = 0; i < 4; i++) {
        float lo[4], hi[4];
#pragma unroll
        for (int j = 0; j < 4; j++) UNPACK2(lo[j], hi[j], acc2[i][j]);
        int r0 = bm + ty * 8 + i * 2;
        float4 o0, o1;
        o0.x = lo[0] + bj[0]; o0.y = lo[1] + bj[1];
        o0.z = lo[2] + bj[2]; o0.w = lo[3] + bj[3];
        o1.x = hi[0] + bj[0]; o1.y = hi[1] + bj[1];
        o1.z = hi[2] + bj[2]; o1.w = hi[3] + bj[3];
        *(float4*)&dst[(r0)     * DIM + bn + tx * 4] = o0;
        *(float4*)&dst[(r0 + 1) * DIM + bn + tx * 4] = o1;
    }
}

// ------------- block reduction helper (128 threads) -------------
__device__ __forceinline__ void reduce2_128(float& s, float& q, float* sh) {
#pragma unroll
    for (int off = 16; off; off >>= 1) {
        s += __shfl_down_sync(0xFFFFFFFFu, s, off);
        q += __shfl_down_sync(0xFFFFFFFFu, q, off);
    }
    int w = threadIdx.x >> 5;
    if ((threadIdx.x & 31) == 0) { sh[w] = s; sh[4 + w] = q; }
    __syncthreads();
    s = sh[0] + sh[1] + sh[2] + sh[3];
    q = sh[4] + sh[5] + sh[6] + sh[7];
}

// ============================================================
// LN1 + ReLU: g_y1 -> g_x1.  128 threads/row, float4.
// ============================================================
__global__ __launch_bounds__(128)
void ln_relu_kernel(const float* __restrict__ g,
                    const float* __restrict__ b) {
    __shared__ float sh[8];
    int row = blockIdx.x;
    int tid = threadIdx.x;
    float4 v = ((const float4*)(g_y1 + row * DIM))[tid];
    float s = v.x + v.y + v.z + v.w;
    float q = v.x * v.x + v.y * v.y + v.z * v.z + v.w * v.w;
    reduce2_128(s, q, sh);
    float mean = s * (1.f / DIM);
    float var  = q * (1.f / DIM) - mean * mean;
    float rstd = rsqrtf(var + LN_EPS);
    float4 gg = ((const float4*)g)[tid];
    float4 bb = ((const float4*)b)[tid];
    float4 o;
    o.x = fmaxf((v.x - mean) * rstd * gg.x + bb.x, 0.f);
    o.y = fmaxf((v.y - mean) * rstd * gg.y + bb.y, 0.f);
    o.z = fmaxf((v.z - mean) * rstd * gg.z + bb.z, 0.f);
    o.w = fmaxf((v.w - mean) * rstd * gg.w + bb.w, 0.f);
    ((float4*)(g_x1 + row * DIM))[tid] = o;
}

// ============================================================
// LN2 + ReLU + linear + duration: g_y2 -> g_dur (x2 never stored)
// ============================================================
__global__ __launch_bounds__(128)
void ln_dur_kernel(const float* __restrict__ g,
                   const float* __restrict__ b,
                   const float* __restrict__ lw,
                   const float* __restrict__ lb) {
    __shared__ float sh[8];
    int row = blockIdx.x;
    int tid = threadIdx.x;
    float4 v = ((const float4*)(g_y2 + row * DIM))[tid];
    float s = v.x + v.y + v.z + v.w;
    float q = v.x * v.x + v.y * v.y + v.z * v.z + v.w * v.w;
    reduce2_128(s, q, sh);
    float mean = s * (1.f / DIM);
    float var  = q * (1.f / DIM) - mean * mean;
    float rstd = rsqrtf(var + LN_EPS);
    float4 gg = ((const float4*)g)[tid];
    float4 bb = ((const float4*)b)[tid];
    float4 ww = ((const float4*)lw)[tid];
    float ox = fmaxf((v.x - mean) * rstd * gg.x + bb.x, 0.f);
    float oy = fmaxf((v.y - mean) * rstd * gg.y + bb.y, 0.f);
    float oz = fmaxf((v.z - mean) * rstd * gg.z + bb.z, 0.f);
    float ow = fmaxf((v.w - mean) * rstd * gg.w + bb.w, 0.f);
    float t = ox * ww.x + oy * ww.y + oz * ww.z + ow * ww.w;
    __syncthreads();   // protect sh reuse
    float dummy = 0.f;
    reduce2_128(t, dummy, sh);
    if (tid == 0) {
        float pred = fmaxf(t + lb[0], 0.f);
        g_dur[row] = (int)floorf(pred + 0.5f);
    }
}

// ============================================================
// Inclusive cumsum of g_dur (4096 ints), single block.
// ============================================================
__global__ __launch_bounds__(1024)
void cumsum_kernel() {
    __shared__ int part[1024];
    int tid = threadIdx.x;
    int v[4];
    int s = 0;
#pragma unroll
    for (int i = 0; i < 4; i++) { v[i] = g_dur[tid * 4 + i]; s += v[i]; }
    part[tid] = s;
    __syncthreads();
    for (int off = 1; off < 1024; off <<= 1) {
        int t = 0;
        if (tid >= off) t = part[tid - off];
        __syncthreads();
        if (tid >= off) part[tid] += t;
        __syncthreads();
    }
    int run = (tid > 0) ? part[tid - 1] : 0;
#pragma unroll
    for (int i = 0; i < 4; i++) { run += v[i]; g_cum[tid * 4 + i] = run; }
}

// ============================================================
// Length regulation: one block per output frame t.
// ============================================================
__global__ __launch_bounds__(128)
void gather_kernel(const float* __restrict__ enc,
                   float* __restrict__ out,
                   float* __restrict__ pos,
                   int write_pos) {
    int t = blockIdx.x;
    int tid = threadIdx.x;
    int total = g_cum[SEQ - 1];
    float4 val = make_float4(0.f, 0.f, 0.f, 0.f);
    if (t < total) {
        int lo = 0, hi = SEQ;
        while (lo < hi) {
            int mid = (lo + hi) >> 1;
            if (g_cum[mid] <= t) lo = mid + 1; else hi = mid;
        }
        if (lo > SEQ - 1) lo = SEQ - 1;
        val = ((const float4*)(enc + lo * DIM))[tid];
    }
    ((float4*)(out + t * DIM))[tid] = val;
    if (write_pos && tid == 0) pos[t] = (float)(t + 1);
}

// ============================================================
extern "C" void kernel_launch(void* const* d_in, const int* in_sizes, int n_in,
                              void* d_out, int out_size) {
    const float* enc = (const float*)d_in[0];
    const float* c1w = (const float*)d_in[1];
    const float* c1b = (const float*)d_in[2];
    const float* g1  = (const float*)d_in[3];
    const float* b1  = (const float*)d_in[4];
    const float* c2w = (const float*)d_in[5];
    const float* c2b = (const float*)d_in[6];
    const float* g2  = (const float*)d_in[7];
    const float* b2  = (const float*)d_in[8];
    const float* lw  = (const float*)d_in[9];
    const float* lb  = (const float*)d_in[10];
    float* out = (float*)d_out;

    wtrans_kernel<<<dim3((KTOT * DIM) / 256, 2), 256>>>(c1w, c2w);
    conv_gemm_kernel<0><<<dim3(SEQ / 128, DIM / 64), 256>>>(enc, c1b);
    ln_relu_kernel<<<SEQ, 128>>>(g1, b1);
    conv_gemm_kernel<1><<<dim3(SEQ / 128, DIM / 64), 256>>>(enc, c2b);
    ln_dur_kernel<<<SEQ, 128>>>(g2, b2, lw, lb);
    cumsum_kernel<<<1, 1024>>>();

    int write_pos = (out_size >= MAXOUT * DIM + MAXOUT) ? 1 : 0;
    gather_kernel<<<MAXOUT, 128>>>(enc, out, out + (size_t)MAXOUT * DIM, write_pos);
}

// round 7
// speedup vs baseline: 1.5164x; 1.1066x over previous
#include <cuda_runtime.h>
#include <cuda_bf16.h>
#include <math.h>

#define SEQ   4096
#define DIM   512
#define KCONV 3
#define KTOT  (DIM * KCONV)      // 1536
#define KHALF (KTOT / 2)         // 768
#define MAXOUT (4 * SEQ)         // 16384
#define LN_EPS 1e-5f

// packed fp32x2 FMA (Blackwell FFMA2) — full fp32 precision per lane
#define FMA_F32X2(d, a, b, c) \
    asm("fma.rn.f32x2 %0, %1, %2, %3;" : "=l"(d) : "l"(a), "l"(b), "l"(c))
#define PACK2(d, lo, hi) \
    asm("mov.b64 %0, {%1, %2};" : "=l"(d) : "f"(lo), "f"(hi))
#define UNPACK2(lo, hi, v) \
    asm("mov.b64 {%0, %1}, %2;" : "=f"(lo), "=f"(hi) : "l"(v))

// -------- scratch (no allocations allowed) --------
__device__ float g_Bt1[KTOT * DIM];   // conv1 weights as [K=1536][N=512]
__device__ float g_Bt2[KTOT * DIM];   // conv2 weights as [K=1536][N=512]
__device__ float g_p0[SEQ * DIM];     // split-K partial 0
__device__ float g_p1[SEQ * DIM];     // split-K partial 1
__device__ float g_x1[SEQ * DIM];     // LN1+ReLU output
__device__ int   g_dur[SEQ];
__device__ int   g_cum[SEQ];

// ============================================================
// Weight permute: w[o][d][k] -> Bt[k*512+d][o]
// ============================================================
__global__ void wtrans_kernel(const float* __restrict__ w1,
                              const float* __restrict__ w2) {
    int idx = blockIdx.x * 256 + threadIdx.x;       // 0 .. 786431
    const float* w = blockIdx.y ? w2 : w1;
    float* Bt      = blockIdx.y ? g_Bt2 : g_Bt1;
    int o = idx & 511;
    int c = idx >> 9;          // 0..1535
    int k = c >> 9;            // 0..2
    int d = c & 511;
    Bt[idx] = w[o * KTOT + d * KCONV + k];
}

// ============================================================
// Conv-as-GEMM, split-K=2: p[z][s][o] = sum_{c in half z} A[s][c]*Bt[c][o]
// A[s][k*512+d] = src[s+k-1][d] (zero padded), implicit im2col.
// BM=128, BN=128, BK=16, 256 threads, 8x8 microtile in FFMA2.
// grid = 32 x 4 x 2 = 256 CTAs.
// ============================================================
template <int PASS>
__global__ __launch_bounds__(256, 2)
void conv_gemm_kernel(const float* __restrict__ enc) {
    const float* src = (PASS == 0) ? enc : g_x1;
    const float* Bt  = (PASS == 0) ? g_Bt1 : g_Bt2;
    float* dst       = blockIdx.z ? g_p1 : g_p0;

    __shared__ float As[16][132];   // [BK][BM+pad]
    __shared__ float Bs[16][128];   // [BK][BN]

    const int bm = blockIdx.x * 128;
    const int bn = blockIdx.y * 128;
    const int kbeg = blockIdx.z * KHALF;
    const int tid = threadIdx.x;
    const int tx = tid & 15;        // 0..15 -> n (8 cols each)
    const int ty = tid >> 4;        // 0..15 -> m (8 rows each)

    // B global/store mapping: 2 float4 per thread
    const int kkB = tid >> 5;             // 0..7
    const int nB4 = (tid & 31) * 4;       // 0..124

    // acc2[ip][j]: M-pair ip (rows 2ip,2ip+1 of the 8), N col j (8 cols)
    unsigned long long acc2[4][8];
#pragma unroll
    for (int i = 0; i < 4; i++)
#pragma unroll
        for (int j = 0; j < 8; j++) acc2[i][j] = 0ull;

#pragma unroll 1
    for (int k0 = kbeg; k0 < kbeg + KHALF; k0 += 16) {
        const int kseg  = k0 >> 9;
        const int dbase = k0 & 511;
        // load A tile (implicit shifted rows of src): 8 scalars/thread
#pragma unroll
        for (int i = 0; i < 8; i++) {
            int e  = tid + i * 256;      // 0..2047
            int kk = e & 15;
            int r  = e >> 4;             // 0..127
            int srow = bm + r + kseg - 1;
            float v = 0.f;
            if (srow >= 0 && srow < SEQ) v = src[srow * DIM + dbase + kk];
            As[kk][r] = v;
        }
        // load B tile: 2 float4/thread
        *(float4*)&Bs[kkB][nB4]     = *(const float4*)&Bt[(k0 + kkB) * DIM + bn + nB4];
        *(float4*)&Bs[kkB + 8][nB4] = *(const float4*)&Bt[(k0 + kkB + 8) * DIM + bn + nB4];
        __syncthreads();

#pragma unroll
        for (int kk = 0; kk < 16; kk++) {
            ulonglong2 a01 = *(const ulonglong2*)&As[kk][ty * 8];
            ulonglong2 a23 = *(const ulonglong2*)&As[kk][ty * 8 + 4];
            unsigned long long am[4] = {a01.x, a01.y, a23.x, a23.y};
            float4 b0 = *(const float4*)&Bs[kk][tx * 8];
            float4 b1 = *(const float4*)&Bs[kk][tx * 8 + 4];
            unsigned long long bb[8];
            PACK2(bb[0], b0.x, b0.x);
            PACK2(bb[1], b0.y, b0.y);
            PACK2(bb[2], b0.z, b0.z);
            PACK2(bb[3], b0.w, b0.w);
            PACK2(bb[4], b1.x, b1.x);
            PACK2(bb[5], b1.y, b1.y);
            PACK2(bb[6], b1.z, b1.z);
            PACK2(bb[7], b1.w, b1.w);
#pragma unroll
            for (int i = 0; i < 4; i++)
#pragma unroll
                for (int j = 0; j < 8; j++)
                    FMA_F32X2(acc2[i][j], am[i], bb[j], acc2[i][j]);
        }
        __syncthreads();
    }

    // ---- epilogue: unpack pairs, store partials (bias added in LN stage)
#pragma unroll
    for (int ip = 0; ip < 4; ip++) {
        float lo[8], hi[8];
#pragma unroll
        for (int j = 0; j < 8; j++) UNPACK2(lo[j], hi[j], acc2[ip][j]);
        int r0 = bm + ty * 8 + ip * 2;
        float4 o;
        o.x = lo[0]; o.y = lo[1]; o.z = lo[2]; o.w = lo[3];
        *(float4*)&dst[r0 * DIM + bn + tx * 8] = o;
        o.x = lo[4]; o.y = lo[5]; o.z = lo[6]; o.w = lo[7];
        *(float4*)&dst[r0 * DIM + bn + tx * 8 + 4] = o;
        o.x = hi[0]; o.y = hi[1]; o.z = hi[2]; o.w = hi[3];
        *(float4*)&dst[(r0 + 1) * DIM + bn + tx * 8] = o;
        o.x = hi[4]; o.y = hi[5]; o.z = hi[6]; o.w = hi[7];
        *(float4*)&dst[(r0 + 1) * DIM + bn + tx * 8 + 4] = o;
    }
}

// ------------- block reduction helper (128 threads) -------------
__device__ __forceinline__ void reduce2_128(float& s, float& q, float* sh) {
#pragma unroll
    for (int off = 16; off; off >>= 1) {
        s += __shfl_down_sync(0xFFFFFFFFu, s, off);
        q += __shfl_down_sync(0xFFFFFFFFu, q, off);
    }
    int w = threadIdx.x >> 5;
    if ((threadIdx.x & 31) == 0) { sh[w] = s; sh[4 + w] = q; }
    __syncthreads();
    s = sh[0] + sh[1] + sh[2] + sh[3];
    q = sh[4] + sh[5] + sh[6] + sh[7];
}

// ============================================================
// Split-K reduce + bias + LN1 + ReLU: (g_p0+g_p1+cb) -> g_x1.
// ============================================================
__global__ __launch_bounds__(128)
void ln_relu_kernel(const float* __restrict__ g,
                    const float* __restrict__ b,
                    const float* __restrict__ cb) {
    __shared__ float sh[8];
    int row = blockIdx.x;
    int tid = threadIdx.x;
    float4 p0 = ((const float4*)(g_p0 + row * DIM))[tid];
    float4 p1 = ((const float4*)(g_p1 + row * DIM))[tid];
    float4 cbv = ((const float4*)cb)[tid];
    float4 v;
    v.x = p0.x + p1.x + cbv.x;
    v.y = p0.y + p1.y + cbv.y;
    v.z = p0.z + p1.z + cbv.z;
    v.w = p0.w + p1.w + cbv.w;
    float s = v.x + v.y + v.z + v.w;
    float q = v.x * v.x + v.y * v.y + v.z * v.z + v.w * v.w;
    reduce2_128(s, q, sh);
    float mean = s * (1.f / DIM);
    float var  = q * (1.f / DIM) - mean * mean;
    float rstd = rsqrtf(var + LN_EPS);
    float4 gg = ((const float4*)g)[tid];
    float4 bb = ((const float4*)b)[tid];
    float4 o;
    o.x = fmaxf((v.x - mean) * rstd * gg.x + bb.x, 0.f);
    o.y = fmaxf((v.y - mean) * rstd * gg.y + bb.y, 0.f);
    o.z = fmaxf((v.z - mean) * rstd * gg.z + bb.z, 0.f);
    o.w = fmaxf((v.w - mean) * rstd * gg.w + bb.w, 0.f);
    ((float4*)(g_x1 + row * DIM))[tid] = o;
}

// ============================================================
// Split-K reduce + bias + LN2 + ReLU + linear + duration -> g_dur
// ============================================================
__global__ __launch_bounds__(128)
void ln_dur_kernel(const float* __restrict__ g,
                   const float* __restrict__ b,
                   const float* __restrict__ lw,
                   const float* __restrict__ lb,
                   const float* __restrict__ cb) {
    __shared__ float sh[8];
    int row = blockIdx.x;
    int tid = threadIdx.x;
    float4 p0 = ((const float4*)(g_p0 + row * DIM))[tid];
    float4 p1 = ((const float4*)(g_p1 + row * DIM))[tid];
    float4 cbv = ((const float4*)cb)[tid];
    float4 v;
    v.x = p0.x + p1.x + cbv.x;
    v.y = p0.y + p1.y + cbv.y;
    v.z = p0.z + p1.z + cbv.z;
    v.w = p0.w + p1.w + cbv.w;
    float s = v.x + v.y + v.z + v.w;
    float q = v.x * v.x + v.y * v.y + v.z * v.z + v.w * v.w;
    reduce2_128(s, q, sh);
    float mean = s * (1.f / DIM);
    float var  = q * (1.f / DIM) - mean * mean;
    float rstd = rsqrtf(var + LN_EPS);
    float4 gg = ((const float4*)g)[tid];
    float4 bb = ((const float4*)b)[tid];
    float4 ww = ((const float4*)lw)[tid];
    float ox = fmaxf((v.x - mean) * rstd * gg.x + bb.x, 0.f);
    float oy = fmaxf((v.y - mean) * rstd * gg.y + bb.y, 0.f);
    float oz = fmaxf((v.z - mean) * rstd * gg.z + bb.z, 0.f);
    float ow = fmaxf((v.w - mean) * rstd * gg.w + bb.w, 0.f);
    float t = ox * ww.x + oy * ww.y + oz * ww.z + ow * ww.w;
    __syncthreads();   // protect sh reuse
    float dummy = 0.f;
    reduce2_128(t, dummy, sh);
    if (tid == 0) {
        float pred = fmaxf(t + lb[0], 0.f);
        g_dur[row] = (int)floorf(pred + 0.5f);
    }
}

// ============================================================
// Inclusive cumsum of g_dur (4096 ints), single block.
// ============================================================
__global__ __launch_bounds__(1024)
void cumsum_kernel() {
    __shared__ int part[1024];
    int tid = threadIdx.x;
    int v[4];
    int s = 0;
#pragma unroll
    for (int i = 0; i < 4; i++) { v[i] = g_dur[tid * 4 + i]; s += v[i]; }
    part[tid] = s;
    __syncthreads();
    for (int off = 1; off < 1024; off <<= 1) {
        int t = 0;
        if (tid >= off) t = part[tid - off];
        __syncthreads();
        if (tid >= off) part[tid] += t;
        __syncthreads();
    }
    int run = (tid > 0) ? part[tid - 1] : 0;
#pragma unroll
    for (int i = 0; i < 4; i++) { run += v[i]; g_cum[tid * 4 + i] = run; }
}

// ============================================================
// Length regulation: one block per output frame t.
// ============================================================
__global__ __launch_bounds__(128)
void gather_kernel(const float* __restrict__ enc,
                   float* __restrict__ out,
                   float* __restrict__ pos,
                   int write_pos) {
    int t = blockIdx.x;
    int tid = threadIdx.x;
    int total = g_cum[SEQ - 1];
    float4 val = make_float4(0.f, 0.f, 0.f, 0.f);
    if (t < total) {
        int lo = 0, hi = SEQ;
        while (lo < hi) {
            int mid = (lo + hi) >> 1;
            if (g_cum[mid] <= t) lo = mid + 1; else hi = mid;
        }
        if (lo > SEQ - 1) lo = SEQ - 1;
        val = ((const float4*)(enc + lo * DIM))[tid];
    }
    ((float4*)(out + t * DIM))[tid] = val;
    if (write_pos && tid == 0) pos[t] = (float)(t + 1);
}

// ============================================================
extern "C" void kernel_launch(void* const* d_in, const int* in_sizes, int n_in,
                              void* d_out, int out_size) {
    const float* enc = (const float*)d_in[0];
    const float* c1w = (const float*)d_in[1];
    const float* c1b = (const float*)d_in[2];
    const float* g1  = (const float*)d_in[3];
    const float* b1  = (const float*)d_in[4];
    const float* c2w = (const float*)d_in[5];
    const float* c2b = (const float*)d_in[6];
    const float* g2  = (const float*)d_in[7];
    const float* b2  = (const float*)d_in[8];
    const float* lw  = (const float*)d_in[9];
    const float* lb  = (const float*)d_in[10];
    float* out = (float*)d_out;

    wtrans_kernel<<<dim3((KTOT * DIM) / 256, 2), 256>>>(c1w, c2w);
    conv_gemm_kernel<0><<<dim3(SEQ / 128, DIM / 128, 2), 256>>>(enc);
    ln_relu_kernel<<<SEQ, 128>>>(g1, b1, c1b);
    conv_gemm_kernel<1><<<dim3(SEQ / 128, DIM / 128, 2), 256>>>(enc);
    ln_dur_kernel<<<SEQ, 128>>>(g2, b2, lw, lb, c2b);
    cumsum_kernel<<<1, 1024>>>();

    int write_pos = (out_size >= MAXOUT * DIM + MAXOUT) ? 1 : 0;
    gather_kernel<<<MAXOUT, 128>>>(enc, out, out + (size_t)MAXOUT * DIM, write_pos);
}

// round 12
// speedup vs baseline: 1.5435x; 1.0179x over previous
#include <cuda_runtime.h>
#include <cuda_bf16.h>
#include <cstdint>
#include <math.h>

#define SEQ   4096
#define DIM   512
#define KCONV 3
#define KTOT  1536
#define MAXOUT 16384
#define LN_EPS 1e-5f
#define BK    64
#define NPROD 6
#define NKT   (KTOT / BK)            // 24 tiles per product
#define NTILES (NPROD * NKT)         // 144 extended-K tiles
#define ATILE 16384                  // 128 rows x 128 B
#define BTILE 16384                  // 128 rows x 128 B
#define SMEM_DYN (2 * ATILE + 2 * BTILE)   // 64 KB

// -------- scratch (no allocations allowed) --------
__device__ __nv_bfloat16 g_e[3][SEQ * DIM];       // enc limbs
__device__ __nv_bfloat16 g_xs[3][SEQ * DIM];      // x1 limbs
__device__ __nv_bfloat16 g_Bw[2][3][DIM * KTOT];  // weight limbs [conv][limb][n*1536+c]
__device__ float g_y[SEQ * DIM];                  // conv output (fp32)
__device__ int   g_dur[SEQ];
__device__ int   g_cum[SEQ];

static __device__ __forceinline__ uint32_t smem_u32(const void* p) {
    uint32_t a;
    asm("{ .reg .u64 t; cvta.to.shared.u64 t, %1; cvt.u32.u64 %0, t; }"
        : "=r"(a) : "l"(p));
    return a;
}

static __device__ __forceinline__ void split3(float v, __nv_bfloat16& h0,
                                              __nv_bfloat16& h1, __nv_bfloat16& h2) {
    h0 = __float2bfloat16(v);
    float r = v - __bfloat162float(h0);
    h1 = __float2bfloat16(r);
    float r2 = r - __bfloat162float(h1);
    h2 = __float2bfloat16(r2);
}

// ============================================================
// enc fp32 -> 3 bf16 limb arrays. float4/thread.
// ============================================================
__global__ void split_enc_kernel(const float* __restrict__ e) {
    int i = blockIdx.x * 256 + threadIdx.x;        // float4 index
    float4 v = ((const float4*)e)[i];
    float a[4] = {v.x, v.y, v.z, v.w};
    __nv_bfloat16 h0[4], h1[4], h2[4];
#pragma unroll
    for (int j = 0; j < 4; j++) split3(a[j], h0[j], h1[j], h2[j]);
    __nv_bfloat162 t;
    t.x = h0[0]; t.y = h0[1]; ((__nv_bfloat162*)g_e[0])[i * 2] = t;
    t.x = h0[2]; t.y = h0[3]; ((__nv_bfloat162*)g_e[0])[i * 2 + 1] = t;
    t.x = h1[0]; t.y = h1[1]; ((__nv_bfloat162*)g_e[1])[i * 2] = t;
    t.x = h1[2]; t.y = h1[3]; ((__nv_bfloat162*)g_e[1])[i * 2 + 1] = t;
    t.x = h2[0]; t.y = h2[1]; ((__nv_bfloat162*)g_e[2])[i * 2] = t;
    t.x = h2[2]; t.y = h2[3]; ((__nv_bfloat162*)g_e[2])[i * 2 + 1] = t;
}

// ============================================================
// weights: w[o][d][k] -> limbs at [o][c], c = k*512+d (K-major rows)
// ============================================================
__global__ void wsplit_kernel(const float* __restrict__ w1,
                              const float* __restrict__ w2) {
    int idx = blockIdx.x * 256 + threadIdx.x;      // o*1536 + c
    int conv = blockIdx.y;
    const float* w = conv ? w2 : w1;
    int o = idx / KTOT;
    int c = idx - o * KTOT;
    int k = c >> 9;
    int d = c & 511;
    float v = w[o * KTOT + d * KCONV + k];
    __nv_bfloat16 h0, h1, h2;
    split3(v, h0, h1, h2);
    g_Bw[conv][0][idx] = h0;
    g_Bw[conv][1][idx] = h1;
    g_Bw[conv][2][idx] = h2;
}

// ---------------- mma.sync building blocks (sm_80 class) ----------------
static __device__ __forceinline__ void ldsm4(uint32_t& r0, uint32_t& r1,
                                             uint32_t& r2, uint32_t& r3,
                                             uint32_t addr) {
    asm volatile("ldmatrix.sync.aligned.m8n8.x4.shared.b16 {%0,%1,%2,%3}, [%4];"
                 : "=r"(r0), "=r"(r1), "=r"(r2), "=r"(r3) : "r"(addr));
}
static __device__ __forceinline__ void mma16816(float* c, const uint32_t* a,
                                                uint32_t b0, uint32_t b1) {
    asm volatile(
        "mma.sync.aligned.m16n8k16.row.col.f32.bf16.bf16.f32 "
        "{%0,%1,%2,%3}, {%4,%5,%6,%7}, {%8,%9}, {%0,%1,%2,%3};"
        : "+f"(c[0]), "+f"(c[1]), "+f"(c[2]), "+f"(c[3])
        : "r"(a[0]), "r"(a[1]), "r"(a[2]), "r"(a[3]), "r"(b0), "r"(b1));
}
static __device__ __forceinline__ void cp16(uint32_t dst, const void* src,
                                            uint32_t srcsz) {
    asm volatile("cp.async.ca.shared.global [%0], [%1], 16, %2;"
                 :: "r"(dst), "l"(src), "r"(srcsz) : "memory");
}

// product -> (A limb, B limb): a0b0, a0b1, a1b0, a0b2, a1b1, a2b0
__constant__ int c_pa[NPROD] = {0, 0, 1, 0, 1, 2};
__constant__ int c_pb[NPROD] = {0, 1, 0, 2, 1, 0};

// ============================================================
// Conv-as-GEMM on mma.sync (HMMA), bf16x3 limbs as extended-K.
// BM=128, BN=128, BK=64, 256 threads (8 warps, each 32Mx64N).
// grid (32, 4) = 128 CTAs. Double-buffered cp.async.
// ============================================================
template <int PASS>
__global__ __launch_bounds__(256, 1)
void conv_mma_kernel() {
    extern __shared__ char ds[];
    const uint32_t sA = smem_u32(ds);                // A buffers: 2 x 16KB
    const uint32_t sB = sA + 2 * ATILE;              // B buffers: 2 x 16KB

    const int tid = threadIdx.x;
    const int wid = tid >> 5;
    const int lane = tid & 31;
    const int bm = blockIdx.x * 128;
    const int bn = blockIdx.y * 128;

    const int wm = wid >> 1;        // 0..3  -> M offset wm*32
    const int wn = wid & 1;         // 0..1  -> N offset wn*64

    float acc[2][8][4];
#pragma unroll
    for (int i = 0; i < 2; i++)
#pragma unroll
        for (int j = 0; j < 8; j++)
#pragma unroll
            for (int q = 0; q < 4; q++) acc[i][j][q] = 0.f;

    // ---- tile loader: tile kt -> buffer bi
    auto load_tile = [&](int kt, int bi) {
        const int p   = kt / NKT;
        const int t24 = kt - p * NKT;
        const int k0  = t24 * BK;
        const int kseg  = k0 >> 9;
        const int dbase = k0 & 511;
        const __nv_bfloat16* limbA =
            (PASS ? g_xs[c_pa[p]] : g_e[c_pa[p]]);
        const __nv_bfloat16* limbB = g_Bw[PASS][c_pb[p]];
        // A: 1024 16B-chunks (128 rows x 8)
#pragma unroll
        for (int i = 0; i < 4; i++) {
            int cid = tid + i * 256;
            int r = cid >> 3, c = cid & 7;
            int srow = bm + r + kseg - 1;
            uint32_t ok = (srow >= 0 && srow < SEQ) ? 16u : 0u;
            int srowc = srow < 0 ? 0 : (srow >= SEQ ? SEQ - 1 : srow);
            const void* src = limbA + ((long long)srowc * DIM + dbase + c * 8);
            uint32_t dst = sA + bi * ATILE + r * 128 + ((c ^ (r & 7)) * 16);
            cp16(dst, src, ok);
        }
        // B: 1024 16B-chunks (128 n-rows x 8), always in-bounds
#pragma unroll
        for (int i = 0; i < 4; i++) {
            int cid = tid + i * 256;
            int n = cid >> 3, c = cid & 7;
            const void* src = limbB + ((long long)(bn + n) * KTOT + k0 + c * 8);
            uint32_t dst = sB + bi * BTILE + n * 128 + ((c ^ (n & 7)) * 16);
            cp16(dst, src, 16u);
        }
        asm volatile("cp.async.commit_group;" ::: "memory");
    };

    // prologue
    load_tile(0, 0);

    const int rr = lane & 7;
    const int q  = lane >> 3;

#pragma unroll 1
    for (int t = 0; t < NTILES; ++t) {
        const int bi = t & 1;
        if (t + 1 < NTILES) {
            load_tile(t + 1, bi ^ 1);
            asm volatile("cp.async.wait_group 1;" ::: "memory");
        } else {
            asm volatile("cp.async.wait_group 0;" ::: "memory");
        }
        __syncthreads();

        const uint32_t Ab = sA + bi * ATILE;
        const uint32_t Bb = sB + bi * BTILE;
#pragma unroll
        for (int ks = 0; ks < 4; ks++) {
            // A frags: 2 x (16 rows x 16 k)
            uint32_t a[2][4];
#pragma unroll
            for (int mt = 0; mt < 2; mt++) {
                int arow = wm * 32 + mt * 16 + rr + (q & 1) * 8;
                int ach  = 2 * ks + (q >> 1);
                uint32_t ad = Ab + arow * 128 + ((ach ^ (arow & 7)) * 16);
                ldsm4(a[mt][0], a[mt][1], a[mt][2], a[mt][3], ad);
            }
            // B frags: 4 x (16 n x 16 k) -> 8 n8-frags
#pragma unroll
            for (int nt = 0; nt < 4; nt++) {
                int brow = wn * 64 + nt * 16 + rr + (q >> 1) * 8;
                int bch  = 2 * ks + (q & 1);
                uint32_t bd = Bb + brow * 128 + ((bch ^ (brow & 7)) * 16);
                uint32_t b0, b1, b2, b3;
                ldsm4(b0, b1, b2, b3, bd);
#pragma unroll
                for (int mt = 0; mt < 2; mt++) {
                    mma16816(acc[mt][nt * 2],     a[mt], b0, b1);
                    mma16816(acc[mt][nt * 2 + 1], a[mt], b2, b3);
                }
            }
        }
        __syncthreads();
    }

    // ---- epilogue: write fp32 to g_y
#pragma unroll
    for (int mt = 0; mt < 2; mt++) {
#pragma unroll
        for (int j = 0; j < 8; j++) {
            int row = bm + wm * 32 + mt * 16 + (lane >> 2);
            int col = bn + wn * 64 + j * 8 + (lane & 3) * 2;
            float2 v0, v1;
            v0.x = acc[mt][j][0]; v0.y = acc[mt][j][1];
            v1.x = acc[mt][j][2]; v1.y = acc[mt][j][3];
            *(float2*)&g_y[(long long)row * DIM + col] = v0;
            *(float2*)&g_y[(long long)(row + 8) * DIM + col] = v1;
        }
    }
}

// ------------- block reduction helper (128 threads) -------------
__device__ __forceinline__ void reduce2_128(float& s, float& q, float* sh) {
#pragma unroll
    for (int off = 16; off; off >>= 1) {
        s += __shfl_down_sync(0xFFFFFFFFu, s, off);
        q += __shfl_down_sync(0xFFFFFFFFu, q, off);
    }
    int w = threadIdx.x >> 5;
    if ((threadIdx.x & 31) == 0) { sh[w] = s; sh[4 + w] = q; }
    __syncthreads();
    s = sh[0] + sh[1] + sh[2] + sh[3];
    q = sh[4] + sh[5] + sh[6] + sh[7];
}

// ============================================================
// bias + LN1 + ReLU: g_y -> x1 limbs (bf16 x3)
// ============================================================
__global__ __launch_bounds__(128)
void ln_relu_kernel(const float* __restrict__ g,
                    const float* __restrict__ b,
                    const float* __restrict__ cb) {
    __shared__ float sh[8];
    int row = blockIdx.x;
    int tid = threadIdx.x;
    float4 y = ((const float4*)(g_y + (long long)row * DIM))[tid];
    float4 cbv = ((const float4*)cb)[tid];
    float4 v;
    v.x = y.x + cbv.x; v.y = y.y + cbv.y; v.z = y.z + cbv.z; v.w = y.w + cbv.w;
    float s = v.x + v.y + v.z + v.w;
    float q = v.x * v.x + v.y * v.y + v.z * v.z + v.w * v.w;
    reduce2_128(s, q, sh);
    float mean = s * (1.f / DIM);
    float var  = q * (1.f / DIM) - mean * mean;
    float rstd = rsqrtf(var + LN_EPS);
    float4 gg = ((const float4*)g)[tid];
    float4 bb = ((const float4*)b)[tid];
    float ov[4];
    ov[0] = fmaxf((v.x - mean) * rstd * gg.x + bb.x, 0.f);
    ov[1] = fmaxf((v.y - mean) * rstd * gg.y + bb.y, 0.f);
    ov[2] = fmaxf((v.z - mean) * rstd * gg.z + bb.z, 0.f);
    ov[3] = fmaxf((v.w - mean) * rstd * gg.w + bb.w, 0.f);
    __nv_bfloat16 h0[4], h1[4], h2[4];
#pragma unroll
    for (int j = 0; j < 4; j++) split3(ov[j], h0[j], h1[j], h2[j]);
    long long pbase = ((long long)row * DIM) / 2 + tid * 2;
    __nv_bfloat162 t;
    t.x = h0[0]; t.y = h0[1]; ((__nv_bfloat162*)g_xs[0])[pbase] = t;
    t.x = h0[2]; t.y = h0[3]; ((__nv_bfloat162*)g_xs[0])[pbase + 1] = t;
    t.x = h1[0]; t.y = h1[1]; ((__nv_bfloat162*)g_xs[1])[pbase] = t;
    t.x = h1[2]; t.y = h1[3]; ((__nv_bfloat162*)g_xs[1])[pbase + 1] = t;
    t.x = h2[0]; t.y = h2[1]; ((__nv_bfloat162*)g_xs[2])[pbase] = t;
    t.x = h2[2]; t.y = h2[3]; ((__nv_bfloat162*)g_xs[2])[pbase + 1] = t;
}

// ============================================================
// bias + LN2 + ReLU + linear + duration -> g_dur
// ============================================================
__global__ __launch_bounds__(128)
void ln_dur_kernel(const float* __restrict__ g,
                   const float* __restrict__ b,
                   const float* __restrict__ lw,
                   const float* __restrict__ lb,
                   const float* __restrict__ cb) {
    __shared__ float sh[8];
    int row = blockIdx.x;
    int tid = threadIdx.x;
    float4 y = ((const float4*)(g_y + (long long)row * DIM))[tid];
    float4 cbv = ((const float4*)cb)[tid];
    float4 v;
    v.x = y.x + cbv.x; v.y = y.y + cbv.y; v.z = y.z + cbv.z; v.w = y.w + cbv.w;
    float s = v.x + v.y + v.z + v.w;
    float q = v.x * v.x + v.y * v.y + v.z * v.z + v.w * v.w;
    reduce2_128(s, q, sh);
    float mean = s * (1.f / DIM);
    float var  = q * (1.f / DIM) - mean * mean;
    float rstd = rsqrtf(var + LN_EPS);
    float4 gg = ((const float4*)g)[tid];
    float4 bb = ((const float4*)b)[tid];
    float4 ww = ((const float4*)lw)[tid];
    float ox = fmaxf((v.x - mean) * rstd * gg.x + bb.x, 0.f);
    float oy = fmaxf((v.y - mean) * rstd * gg.y + bb.y, 0.f);
    float oz = fmaxf((v.z - mean) * rstd * gg.z + bb.z, 0.f);
    float ow = fmaxf((v.w - mean) * rstd * gg.w + bb.w, 0.f);
    float t = ox * ww.x + oy * ww.y + oz * ww.z + ow * ww.w;
    __syncthreads();
    float dummy = 0.f;
    reduce2_128(t, dummy, sh);
    if (tid == 0) {
        float pred = fmaxf(t + lb[0], 0.f);
        g_dur[row] = (int)floorf(pred + 0.5f);
    }
}

// ============================================================
// Inclusive cumsum of g_dur (4096 ints), single block.
// ============================================================
__global__ __launch_bounds__(1024)
void cumsum_kernel() {
    __shared__ int part[1024];
    int tid = threadIdx.x;
    int v[4];
    int s = 0;
#pragma unroll
    for (int i = 0; i < 4; i++) { v[i] = g_dur[tid * 4 + i]; s += v[i]; }
    part[tid] = s;
    __syncthreads();
    for (int off = 1; off < 1024; off <<= 1) {
        int t = 0;
        if (tid >= off) t = part[tid - off];
        __syncthreads();
        if (tid >= off) part[tid] += t;
        __syncthreads();
    }
    int run = (tid > 0) ? part[tid - 1] : 0;
#pragma unroll
    for (int i = 0; i < 4; i++) { run += v[i]; g_cum[tid * 4 + i] = run; }
}

// ============================================================
// Length regulation: one block per output frame t.
// ============================================================
__global__ __launch_bounds__(128)
void gather_kernel(const float* __restrict__ enc,
                   float* __restrict__ out,
                   float* __restrict__ pos,
                   int write_pos) {
    int t = blockIdx.x;
    int tid = threadIdx.x;
    int total = g_cum[SEQ - 1];
    float4 val = make_float4(0.f, 0.f, 0.f, 0.f);
    if (t < total) {
        int lo = 0, hi = SEQ;
        while (lo < hi) {
            int mid = (lo + hi) >> 1;
            if (g_cum[mid] <= t) lo = mid + 1; else hi = mid;
        }
        if (lo > SEQ - 1) lo = SEQ - 1;
        val = ((const float4*)(enc + (long long)lo * DIM))[tid];
    }
    ((float4*)(out + (long long)t * DIM))[tid] = val;
    if (write_pos && tid == 0) pos[t] = (float)(t + 1);
}

// ============================================================
extern "C" void kernel_launch(void* const* d_in, const int* in_sizes, int n_in,
                              void* d_out, int out_size) {
    const float* enc = (const float*)d_in[0];
    const float* c1w = (const float*)d_in[1];
    const float* c1b = (const float*)d_in[2];
    const float* g1  = (const float*)d_in[3];
    const float* b1  = (const float*)d_in[4];
    const float* c2w = (const float*)d_in[5];
    const float* c2b = (const float*)d_in[6];
    const float* g2  = (const float*)d_in[7];
    const float* b2  = (const float*)d_in[8];
    const float* lw  = (const float*)d_in[9];
    const float* lb  = (const float*)d_in[10];
    float* out = (float*)d_out;

    cudaFuncSetAttribute(conv_mma_kernel<0>,
                         cudaFuncAttributeMaxDynamicSharedMemorySize, SMEM_DYN);
    cudaFuncSetAttribute(conv_mma_kernel<1>,
                         cudaFuncAttributeMaxDynamicSharedMemorySize, SMEM_DYN);

    split_enc_kernel<<<SEQ * DIM / 1024, 256>>>(enc);
    wsplit_kernel<<<dim3(KTOT * DIM / 256, 2), 256>>>(c1w, c2w);
    conv_mma_kernel<0><<<dim3(SEQ / 128, DIM / 128), 256, SMEM_DYN>>>();
    ln_relu_kernel<<<SEQ, 128>>>(g1, b1, c1b);
    conv_mma_kernel<1><<<dim3(SEQ / 128, DIM / 128), 256, SMEM_DYN>>>();
    ln_dur_kernel<<<SEQ, 128>>>(g2, b2, lw, lb, c2b);
    cumsum_kernel<<<1, 1024>>>();

    int write_pos = (out_size >= MAXOUT * DIM + MAXOUT) ? 1 : 0;
    gather_kernel<<<MAXOUT, 128>>>(enc, out, out + (size_t)MAXOUT * DIM, write_pos);
}

// round 13
// speedup vs baseline: 2.1255x; 1.3771x over previous
#include <cuda_runtime.h>
#include <cuda_bf16.h>
#include <cstdint>
#include <math.h>

#define SEQ   4096
#define DIM   512
#define KCONV 3
#define KTOT  1536
#define MAXOUT 16384
#define LN_EPS 1e-5f
#define BK    64
#define NKT   (KTOT / BK)            // 24 k-tiles
#define TILEB 16384                  // one operand tile: 128 rows x 128 B
#define BUFB  (6 * TILEB)            // A0,A1,A2,B0,B1,B2 per buffer = 96 KB
#define SMEM_DYN (2 * BUFB)          // 192 KB double-buffered

// -------- scratch (no allocations allowed) --------
__device__ __nv_bfloat16 g_e[3][SEQ * DIM];       // enc limbs
__device__ __nv_bfloat16 g_xs[3][SEQ * DIM];      // x1 limbs
__device__ __nv_bfloat16 g_Bw[2][3][DIM * KTOT];  // weight limbs [conv][limb][n*1536+c]
__device__ float g_y[SEQ * DIM];                  // conv output (fp32)
__device__ int   g_dur[SEQ];
__device__ int   g_cum[SEQ];

static __device__ __forceinline__ uint32_t smem_u32(const void* p) {
    uint32_t a;
    asm("{ .reg .u64 t; cvta.to.shared.u64 t, %1; cvt.u32.u64 %0, t; }"
        : "=r"(a) : "l"(p));
    return a;
}

static __device__ __forceinline__ void split3(float v, __nv_bfloat16& h0,
                                              __nv_bfloat16& h1, __nv_bfloat16& h2) {
    h0 = __float2bfloat16(v);
    float r = v - __bfloat162float(h0);
    h1 = __float2bfloat16(r);
    float r2 = r - __bfloat162float(h1);
    h2 = __float2bfloat16(r2);
}

// ============================================================
// enc fp32 -> 3 bf16 limb arrays. float4/thread.
// ============================================================
__global__ void split_enc_kernel(const float* __restrict__ e) {
    int i = blockIdx.x * 256 + threadIdx.x;        // float4 index
    float4 v = ((const float4*)e)[i];
    float a[4] = {v.x, v.y, v.z, v.w};
    __nv_bfloat16 h0[4], h1[4], h2[4];
#pragma unroll
    for (int j = 0; j < 4; j++) split3(a[j], h0[j], h1[j], h2[j]);
    __nv_bfloat162 t;
    t.x = h0[0]; t.y = h0[1]; ((__nv_bfloat162*)g_e[0])[i * 2] = t;
    t.x = h0[2]; t.y = h0[3]; ((__nv_bfloat162*)g_e[0])[i * 2 + 1] = t;
    t.x = h1[0]; t.y = h1[1]; ((__nv_bfloat162*)g_e[1])[i * 2] = t;
    t.x = h1[2]; t.y = h1[3]; ((__nv_bfloat162*)g_e[1])[i * 2 + 1] = t;
    t.x = h2[0]; t.y = h2[1]; ((__nv_bfloat162*)g_e[2])[i * 2] = t;
    t.x = h2[2]; t.y = h2[3]; ((__nv_bfloat162*)g_e[2])[i * 2 + 1] = t;
}

// ============================================================
// weights: w[o][d][k] -> limbs at [o][c], c = k*512+d (K-major rows)
// ============================================================
__global__ void wsplit_kernel(const float* __restrict__ w1,
                              const float* __restrict__ w2) {
    int idx = blockIdx.x * 256 + threadIdx.x;      // o*1536 + c
    int conv = blockIdx.y;
    const float* w = conv ? w2 : w1;
    int o = idx / KTOT;
    int c = idx - o * KTOT;
    int k = c >> 9;
    int d = c & 511;
    float v = w[o * KTOT + d * KCONV + k];
    __nv_bfloat16 h0, h1, h2;
    split3(v, h0, h1, h2);
    g_Bw[conv][0][idx] = h0;
    g_Bw[conv][1][idx] = h1;
    g_Bw[conv][2][idx] = h2;
}

// ---------------- mma.sync building blocks (sm_80 class) ----------------
static __device__ __forceinline__ void ldsm4(uint32_t& r0, uint32_t& r1,
                                             uint32_t& r2, uint32_t& r3,
                                             uint32_t addr) {
    asm volatile("ldmatrix.sync.aligned.m8n8.x4.shared.b16 {%0,%1,%2,%3}, [%4];"
                 : "=r"(r0), "=r"(r1), "=r"(r2), "=r"(r3) : "r"(addr));
}
static __device__ __forceinline__ void mma16816(float* c, const uint32_t* a,
                                                uint32_t b0, uint32_t b1) {
    asm volatile(
        "mma.sync.aligned.m16n8k16.row.col.f32.bf16.bf16.f32 "
        "{%0,%1,%2,%3}, {%4,%5,%6,%7}, {%8,%9}, {%0,%1,%2,%3};"
        : "+f"(c[0]), "+f"(c[1]), "+f"(c[2]), "+f"(c[3])
        : "r"(a[0]), "r"(a[1]), "r"(a[2]), "r"(a[3]), "r"(b0), "r"(b1));
}
static __device__ __forceinline__ void cp16(uint32_t dst, const void* src,
                                            uint32_t srcsz) {
    asm volatile("cp.async.ca.shared.global [%0], [%1], 16, %2;"
                 :: "r"(dst), "l"(src), "r"(srcsz) : "memory");
}

// ============================================================
// Conv-as-GEMM on mma.sync (HMMA), bf16x3 limbs.
// All 6 limb tiles resident per k0: products {a0b0,a1b0,a2b0,a0b1,a1b1,a0b2}
// issued from shared data. BM=128, BN=128, BK=64, 256 threads
// (8 warps, each 32Mx64N). grid (32, 4) = 128 CTAs. Double-buffered.
// ============================================================
template <int PASS>
__global__ __launch_bounds__(256, 1)
void conv_mma_kernel() {
    extern __shared__ char ds[];
    const uint32_t sBase = smem_u32(ds);

    const int tid = threadIdx.x;
    const int wid = tid >> 5;
    const int lane = tid & 31;
    const int bm = blockIdx.x * 128;
    const int bn = blockIdx.y * 128;

    const int wm = wid >> 1;        // 0..3  -> M offset wm*32
    const int wn = wid & 1;         // 0..1  -> N offset wn*64

    float acc[2][8][4];
#pragma unroll
    for (int i = 0; i < 2; i++)
#pragma unroll
        for (int j = 0; j < 8; j++)
#pragma unroll
            for (int q = 0; q < 4; q++) acc[i][j][q] = 0.f;

    // ---- tile loader: k-tile t24 -> buffer bi (loads all 6 limb tiles)
    auto load_tile = [&](int t24, int bi) {
        const int k0 = t24 * BK;
        const int kseg  = k0 >> 9;
        const int dbase = k0 & 511;
        const uint32_t buf = sBase + bi * BUFB;
        // 6144 16B-chunks over 256 threads = 24 each
#pragma unroll
        for (int i = 0; i < 24; i++) {
            int cid = tid + i * 256;          // 0..6143
            int tile = cid >> 10;             // 0..5
            int w = cid & 1023;
            int r = w >> 3, c = w & 7;        // row 0..127, chunk 0..7
            uint32_t dst = buf + tile * TILEB + r * 128 + ((c ^ (r & 7)) * 16);
            if (tile < 3) {                   // A limb tiles (im2col rows)
                int srow = bm + r + kseg - 1;
                uint32_t ok = (srow >= 0 && srow < SEQ) ? 16u : 0u;
                int srowc = srow < 0 ? 0 : (srow >= SEQ - 1 ? SEQ - 1 : srow);
                const __nv_bfloat16* limbA = PASS ? g_xs[tile] : g_e[tile];
                cp16(dst, limbA + ((long long)srowc * DIM + dbase + c * 8), ok);
            } else {                          // B limb tiles (weights)
                const __nv_bfloat16* limbB = g_Bw[PASS][tile - 3];
                cp16(dst, limbB + ((long long)(bn + r) * KTOT + k0 + c * 8), 16u);
            }
        }
        asm volatile("cp.async.commit_group;" ::: "memory");
    };

    // prologue
    load_tile(0, 0);

    const int rr = lane & 7;
    const int q  = lane >> 3;

#pragma unroll 1
    for (int t = 0; t < NKT; ++t) {
        const int bi = t & 1;
        if (t + 1 < NKT) {
            load_tile(t + 1, bi ^ 1);
            asm volatile("cp.async.wait_group 1;" ::: "memory");
        } else {
            asm volatile("cp.async.wait_group 0;" ::: "memory");
        }
        __syncthreads();

        const uint32_t buf = sBase + bi * BUFB;
#pragma unroll
        for (int ks = 0; ks < 4; ks++) {
            // A frags for all 3 limbs, 2 m16 tiles each
            uint32_t a[3][2][4];
#pragma unroll
            for (int s = 0; s < 3; s++)
#pragma unroll
                for (int mt = 0; mt < 2; mt++) {
                    int arow = wm * 32 + mt * 16 + rr + (q & 1) * 8;
                    int ach  = 2 * ks + (q >> 1);
                    uint32_t ad = buf + s * TILEB + arow * 128 +
                                  ((ach ^ (arow & 7)) * 16);
                    ldsm4(a[s][mt][0], a[s][mt][1], a[s][mt][2], a[s][mt][3], ad);
                }
            // B frags per n16 block and limb; each feeds 2-3 A limbs
#pragma unroll
            for (int nt = 0; nt < 4; nt++) {
#pragma unroll
                for (int j = 0; j < 3; j++) {
                    int brow = wn * 64 + nt * 16 + rr + (q >> 1) * 8;
                    int bch  = 2 * ks + (q & 1);
                    uint32_t bd = buf + (3 + j) * TILEB + brow * 128 +
                                  ((bch ^ (brow & 7)) * 16);
                    uint32_t b0, b1, b2, b3;
                    ldsm4(b0, b1, b2, b3, bd);
                    const int amax = 2 - j;     // j=0:{a0,a1,a2} j=1:{a0,a1} j=2:{a0}
#pragma unroll
                    for (int ai = 0; ai < 3; ai++) {
                        if (ai > amax) break;
#pragma unroll
                        for (int mt = 0; mt < 2; mt++) {
                            mma16816(acc[mt][nt * 2],     a[ai][mt], b0, b1);
                            mma16816(acc[mt][nt * 2 + 1], a[ai][mt], b2, b3);
                        }
                    }
                }
            }
        }
        __syncthreads();
    }

    // ---- epilogue: write fp32 to g_y
#pragma unroll
    for (int mt = 0; mt < 2; mt++) {
#pragma unroll
        for (int j = 0; j < 8; j++) {
            int row = bm + wm * 32 + mt * 16 + (lane >> 2);
            int col = bn + wn * 64 + j * 8 + (lane & 3) * 2;
            float2 v0, v1;
            v0.x = acc[mt][j][0]; v0.y = acc[mt][j][1];
            v1.x = acc[mt][j][2]; v1.y = acc[mt][j][3];
            *(float2*)&g_y[(long long)row * DIM + col] = v0;
            *(float2*)&g_y[(long long)(row + 8) * DIM + col] = v1;
        }
    }
}

// ------------- block reduction helper (128 threads) -------------
__device__ __forceinline__ void reduce2_128(float& s, float& q, float* sh) {
#pragma unroll
    for (int off = 16; off; off >>= 1) {
        s += __shfl_down_sync(0xFFFFFFFFu, s, off);
        q += __shfl_down_sync(0xFFFFFFFFu, q, off);
    }
    int w = threadIdx.x >> 5;
    if ((threadIdx.x & 31) == 0) { sh[w] = s; sh[4 + w] = q; }
    __syncthreads();
    s = sh[0] + sh[1] + sh[2] + sh[3];
    q = sh[4] + sh[5] + sh[6] + sh[7];
}

// ============================================================
// bias + LN1 + ReLU: g_y -> x1 limbs (bf16 x3)
// ============================================================
__global__ __launch_bounds__(128)
void ln_relu_kernel(const float* __restrict__ g,
                    const float* __restrict__ b,
                    const float* __restrict__ cb) {
    __shared__ float sh[8];
    int row = blockIdx.x;
    int tid = threadIdx.x;
    float4 y = ((const float4*)(g_y + (long long)row * DIM))[tid];
    float4 cbv = ((const float4*)cb)[tid];
    float4 v;
    v.x = y.x + cbv.x; v.y = y.y + cbv.y; v.z = y.z + cbv.z; v.w = y.w + cbv.w;
    float s = v.x + v.y + v.z + v.w;
    float q = v.x * v.x + v.y * v.y + v.z * v.z + v.w * v.w;
    reduce2_128(s, q, sh);
    float mean = s * (1.f / DIM);
    float var  = q * (1.f / DIM) - mean * mean;
    float rstd = rsqrtf(var + LN_EPS);
    float4 gg = ((const float4*)g)[tid];
    float4 bb = ((const float4*)b)[tid];
    float ov[4];
    ov[0] = fmaxf((v.x - mean) * rstd * gg.x + bb.x, 0.f);
    ov[1] = fmaxf((v.y - mean) * rstd * gg.y + bb.y, 0.f);
    ov[2] = fmaxf((v.z - mean) * rstd * gg.z + bb.z, 0.f);
    ov[3] = fmaxf((v.w - mean) * rstd * gg.w + bb.w, 0.f);
    __nv_bfloat16 h0[4], h1[4], h2[4];
#pragma unroll
    for (int j = 0; j < 4; j++) split3(ov[j], h0[j], h1[j], h2[j]);
    long long pbase = ((long long)row * DIM) / 2 + tid * 2;
    __nv_bfloat162 t;
    t.x = h0[0]; t.y = h0[1]; ((__nv_bfloat162*)g_xs[0])[pbase] = t;
    t.x = h0[2]; t.y = h0[3]; ((__nv_bfloat162*)g_xs[0])[pbase + 1] = t;
    t.x = h1[0]; t.y = h1[1]; ((__nv_bfloat162*)g_xs[1])[pbase] = t;
    t.x = h1[2]; t.y = h1[3]; ((__nv_bfloat162*)g_xs[1])[pbase + 1] = t;
    t.x = h2[0]; t.y = h2[1]; ((__nv_bfloat162*)g_xs[2])[pbase] = t;
    t.x = h2[2]; t.y = h2[3]; ((__nv_bfloat162*)g_xs[2])[pbase + 1] = t;
}

// ============================================================
// bias + LN2 + ReLU + linear + duration -> g_dur
// ============================================================
__global__ __launch_bounds__(128)
void ln_dur_kernel(const float* __restrict__ g,
                   const float* __restrict__ b,
                   const float* __restrict__ lw,
                   const float* __restrict__ lb,
                   const float* __restrict__ cb) {
    __shared__ float sh[8];
    int row = blockIdx.x;
    int tid = threadIdx.x;
    float4 y = ((const float4*)(g_y + (long long)row * DIM))[tid];
    float4 cbv = ((const float4*)cb)[tid];
    float4 v;
    v.x = y.x + cbv.x; v.y = y.y + cbv.y; v.z = y.z + cbv.z; v.w = y.w + cbv.w;
    float s = v.x + v.y + v.z + v.w;
    float q = v.x * v.x + v.y * v.y + v.z * v.z + v.w * v.w;
    reduce2_128(s, q, sh);
    float mean = s * (1.f / DIM);
    float var  = q * (1.f / DIM) - mean * mean;
    float rstd = rsqrtf(var + LN_EPS);
    float4 gg = ((const float4*)g)[tid];
    float4 bb = ((const float4*)b)[tid];
    float4 ww = ((const float4*)lw)[tid];
    float ox = fmaxf((v.x - mean) * rstd * gg.x + bb.x, 0.f);
    float oy = fmaxf((v.y - mean) * rstd * gg.y + bb.y, 0.f);
    float oz = fmaxf((v.z - mean) * rstd * gg.z + bb.z, 0.f);
    float ow = fmaxf((v.w - mean) * rstd * gg.w + bb.w, 0.f);
    float t = ox * ww.x + oy * ww.y + oz * ww.z + ow * ww.w;
    __syncthreads();
    float dummy = 0.f;
    reduce2_128(t, dummy, sh);
    if (tid == 0) {
        float pred = fmaxf(t + lb[0], 0.f);
        g_dur[row] = (int)floorf(pred + 0.5f);
    }
}

// ============================================================
// Inclusive cumsum of g_dur (4096 ints), single block.
// ============================================================
__global__ __launch_bounds__(1024)
void cumsum_kernel() {
    __shared__ int part[1024];
    int tid = threadIdx.x;
    int v[4];
    int s = 0;
#pragma unroll
    for (int i = 0; i < 4; i++) { v[i] = g_dur[tid * 4 + i]; s += v[i]; }
    part[tid] = s;
    __syncthreads();
    for (int off = 1; off < 1024; off <<= 1) {
        int t = 0;
        if (tid >= off) t = part[tid - off];
        __syncthreads();
        if (tid >= off) part[tid] += t;
        __syncthreads();
    }
    int run = (tid > 0) ? part[tid - 1] : 0;
#pragma unroll
    for (int i = 0; i < 4; i++) { run += v[i]; g_cum[tid * 4 + i] = run; }
}

// ============================================================
// Length regulation: one block per output frame t.
// ============================================================
__global__ __launch_bounds__(128)
void gather_kernel(const float* __restrict__ enc,
                   float* __restrict__ out,
                   float* __restrict__ pos,
                   int write_pos) {
    int t = blockIdx.x;
    int tid = threadIdx.x;
    int total = g_cum[SEQ - 1];
    float4 val = make_float4(0.f, 0.f, 0.f, 0.f);
    if (t < total) {
        int lo = 0, hi = SEQ;
        while (lo < hi) {
            int mid = (lo + hi) >> 1;
            if (g_cum[mid] <= t) lo = mid + 1; else hi = mid;
        }
        if (lo > SEQ - 1) lo = SEQ - 1;
        val = ((const float4*)(enc + (long long)lo * DIM))[tid];
    }
    ((float4*)(out + (long long)t * DIM))[tid] = val;
    if (write_pos && tid == 0) pos[t] = (float)(t + 1);
}

// ============================================================
extern "C" void kernel_launch(void* const* d_in, const int* in_sizes, int n_in,
                              void* d_out, int out_size) {
    const float* enc = (const float*)d_in[0];
    const float* c1w = (const float*)d_in[1];
    const float* c1b = (const float*)d_in[2];
    const float* g1  = (const float*)d_in[3];
    const float* b1  = (const float*)d_in[4];
    const float* c2w = (const float*)d_in[5];
    const float* c2b = (const float*)d_in[6];
    const float* g2  = (const float*)d_in[7];
    const float* b2  = (const float*)d_in[8];
    const float* lw  = (const float*)d_in[9];
    const float* lb  = (const float*)d_in[10];
    float* out = (float*)d_out;

    cudaFuncSetAttribute(conv_mma_kernel<0>,
                         cudaFuncAttributeMaxDynamicSharedMemorySize, SMEM_DYN);
    cudaFuncSetAttribute(conv_mma_kernel<1>,
                         cudaFuncAttributeMaxDynamicSharedMemorySize, SMEM_DYN);

    split_enc_kernel<<<SEQ * DIM / 1024, 256>>>(enc);
    wsplit_kernel<<<dim3(KTOT * DIM / 256, 2), 256>>>(c1w, c2w);
    conv_mma_kernel<0><<<dim3(SEQ / 128, DIM / 128), 256, SMEM_DYN>>>();
    ln_relu_kernel<<<SEQ, 128>>>(g1, b1, c1b);
    conv_mma_kernel<1><<<dim3(SEQ / 128, DIM / 128), 256, SMEM_DYN>>>();
    ln_dur_kernel<<<SEQ, 128>>>(g2, b2, lw, lb, c2b);
    cumsum_kernel<<<1, 1024>>>();

    int write_pos = (out_size >= MAXOUT * DIM + MAXOUT) ? 1 : 0;
    gather_kernel<<<MAXOUT, 128>>>(enc, out, out + (size_t)MAXOUT * DIM, write_pos);
}

// round 14
// speedup vs baseline: 3.1035x; 1.4601x over previous
#include <cuda_runtime.h>
#include <cuda_fp16.h>
#include <cstdint>
#include <math.h>

#define SEQ   4096
#define DIM   512
#define KCONV 3
#define KTOT  1536
#define MAXOUT 16384
#define LN_EPS 1e-5f
#define BK    64
#define NKT   (KTOT / BK)            // 24 k-tiles
#define TILEB 16384                  // one operand tile: 128 rows x 128 B
#define BUFB  (4 * TILEB)            // A0,A1,B0,B1 per buffer = 64 KB
#define SMEM_DYN (2 * BUFB)          // 128 KB double-buffered
#define WSCALE 256.0f
#define WINV   (1.0f / 256.0f)

// -------- scratch (no allocations allowed) --------
__device__ __half g_e[2][SEQ * DIM];        // enc limbs (fp16 x2)
__device__ __half g_xs[2][SEQ * DIM];       // x1 limbs
__device__ __half g_Bw[2][2][DIM * KTOT];   // weight limbs [conv][limb][n*1536+c], pre-scaled x256
__device__ float g_y[SEQ * DIM];            // conv output (fp32)
__device__ int   g_dur[SEQ];
__device__ int   g_cum[SEQ];

static __device__ __forceinline__ uint32_t smem_u32(const void* p) {
    uint32_t a;
    asm("{ .reg .u64 t; cvta.to.shared.u64 t, %1; cvt.u32.u64 %0, t; }"
        : "=r"(a) : "l"(p));
    return a;
}

static __device__ __forceinline__ void split2(float v, __half& h0, __half& h1) {
    h0 = __float2half_rn(v);
    h1 = __float2half_rn(v - __half2float(h0));
}

// ============================================================
// enc fp32 -> 2 fp16 limb arrays. float4/thread.
// ============================================================
__global__ void split_enc_kernel(const float* __restrict__ e) {
    int i = blockIdx.x * 256 + threadIdx.x;        // float4 index
    float4 v = ((const float4*)e)[i];
    float a[4] = {v.x, v.y, v.z, v.w};
    __half h0[4], h1[4];
#pragma unroll
    for (int j = 0; j < 4; j++) split2(a[j], h0[j], h1[j]);
    __half2 t;
    t.x = h0[0]; t.y = h0[1]; ((__half2*)g_e[0])[i * 2] = t;
    t.x = h0[2]; t.y = h0[3]; ((__half2*)g_e[0])[i * 2 + 1] = t;
    t.x = h1[0]; t.y = h1[1]; ((__half2*)g_e[1])[i * 2] = t;
    t.x = h1[2]; t.y = h1[3]; ((__half2*)g_e[1])[i * 2 + 1] = t;
}

// ============================================================
// weights: w[o][d][k]*256 -> limbs at [o][c], c = k*512+d (K-major rows)
// ============================================================
__global__ void wsplit_kernel(const float* __restrict__ w1,
                              const float* __restrict__ w2) {
    int idx = blockIdx.x * 256 + threadIdx.x;      // o*1536 + c
    int conv = blockIdx.y;
    const float* w = conv ? w2 : w1;
    int o = idx / KTOT;
    int c = idx - o * KTOT;
    int k = c >> 9;
    int d = c & 511;
    float v = w[o * KTOT + d * KCONV + k] * WSCALE;
    __half h0, h1;
    split2(v, h0, h1);
    g_Bw[conv][0][idx] = h0;
    g_Bw[conv][1][idx] = h1;
}

// ---------------- mma.sync building blocks (sm_80 class) ----------------
static __device__ __forceinline__ void ldsm4(uint32_t& r0, uint32_t& r1,
                                             uint32_t& r2, uint32_t& r3,
                                             uint32_t addr) {
    asm volatile("ldmatrix.sync.aligned.m8n8.x4.shared.b16 {%0,%1,%2,%3}, [%4];"
                 : "=r"(r0), "=r"(r1), "=r"(r2), "=r"(r3) : "r"(addr));
}
static __device__ __forceinline__ void mma16816(float* c, const uint32_t* a,
                                                uint32_t b0, uint32_t b1) {
    asm volatile(
        "mma.sync.aligned.m16n8k16.row.col.f32.f16.f16.f32 "
        "{%0,%1,%2,%3}, {%4,%5,%6,%7}, {%8,%9}, {%0,%1,%2,%3};"
        : "+f"(c[0]), "+f"(c[1]), "+f"(c[2]), "+f"(c[3])
        : "r"(a[0]), "r"(a[1]), "r"(a[2]), "r"(a[3]), "r"(b0), "r"(b1));
}
static __device__ __forceinline__ void cp16(uint32_t dst, const void* src,
                                            uint32_t srcsz) {
    asm volatile("cp.async.ca.shared.global [%0], [%1], 16, %2;"
                 :: "r"(dst), "l"(src), "r"(srcsz) : "memory");
}

// ============================================================
// Conv-as-GEMM on mma.sync (HMMA), fp16x2 limbs: full product
// (a0+a1)(b0+b1) = 4 MMA products, fp32 accumulate, x(1/256) epilogue.
// BM=128, BN=128, BK=64, 256 threads (8 warps, each 32Mx64N).
// grid (32, 4) = 128 CTAs. Double-buffered cp.async.
// ============================================================
template <int PASS>
__global__ __launch_bounds__(256, 1)
void conv_mma_kernel() {
    extern __shared__ char ds[];
    const uint32_t sBase = smem_u32(ds);

    const int tid = threadIdx.x;
    const int wid = tid >> 5;
    const int lane = tid & 31;
    const int bm = blockIdx.x * 128;
    const int bn = blockIdx.y * 128;

    const int wm = wid >> 1;        // 0..3  -> M offset wm*32
    const int wn = wid & 1;         // 0..1  -> N offset wn*64

    float acc[2][8][4];
#pragma unroll
    for (int i = 0; i < 2; i++)
#pragma unroll
        for (int j = 0; j < 8; j++)
#pragma unroll
            for (int q = 0; q < 4; q++) acc[i][j][q] = 0.f;

    // ---- tile loader: k-tile t24 -> buffer bi (loads 4 limb tiles)
    auto load_tile = [&](int t24, int bi) {
        const int k0 = t24 * BK;
        const int kseg  = k0 >> 9;
        const int dbase = k0 & 511;
        const uint32_t buf = sBase + bi * BUFB;
        // 4096 16B-chunks over 256 threads = 16 each
#pragma unroll
        for (int i = 0; i < 16; i++) {
            int cid = tid + i * 256;          // 0..4095
            int tile = cid >> 10;             // 0..3
            int w = cid & 1023;
            int r = w >> 3, c = w & 7;        // row 0..127, chunk 0..7
            uint32_t dst = buf + tile * TILEB + r * 128 + ((c ^ (r & 7)) * 16);
            if (tile < 2) {                   // A limb tiles (im2col rows)
                int srow = bm + r + kseg - 1;
                uint32_t ok = (srow >= 0 && srow < SEQ) ? 16u : 0u;
                int srowc = srow < 0 ? 0 : (srow >= SEQ ? SEQ - 1 : srow);
                const __half* limbA = PASS ? g_xs[tile] : g_e[tile];
                cp16(dst, limbA + ((long long)srowc * DIM + dbase + c * 8), ok);
            } else {                          // B limb tiles (weights)
                const __half* limbB = g_Bw[PASS][tile - 2];
                cp16(dst, limbB + ((long long)(bn + r) * KTOT + k0 + c * 8), 16u);
            }
        }
        asm volatile("cp.async.commit_group;" ::: "memory");
    };

    // prologue
    load_tile(0, 0);

    const int rr = lane & 7;
    const int q  = lane >> 3;

#pragma unroll 1
    for (int t = 0; t < NKT; ++t) {
        const int bi = t & 1;
        if (t + 1 < NKT) {
            load_tile(t + 1, bi ^ 1);
            asm volatile("cp.async.wait_group 1;" ::: "memory");
        } else {
            asm volatile("cp.async.wait_group 0;" ::: "memory");
        }
        __syncthreads();

        const uint32_t buf = sBase + bi * BUFB;
#pragma unroll
        for (int ks = 0; ks < 4; ks++) {
            // A frags for both limbs, 2 m16 tiles each
            uint32_t a[2][2][4];
#pragma unroll
            for (int s = 0; s < 2; s++)
#pragma unroll
                for (int mt = 0; mt < 2; mt++) {
                    int arow = wm * 32 + mt * 16 + rr + (q & 1) * 8;
                    int ach  = 2 * ks + (q >> 1);
                    uint32_t ad = buf + s * TILEB + arow * 128 +
                                  ((ach ^ (arow & 7)) * 16);
                    ldsm4(a[s][mt][0], a[s][mt][1], a[s][mt][2], a[s][mt][3], ad);
                }
            // B frags per n16 block and limb; each feeds both A limbs
#pragma unroll
            for (int nt = 0; nt < 4; nt++) {
#pragma unroll
                for (int bl = 0; bl < 2; bl++) {
                    int brow = wn * 64 + nt * 16 + rr + (q >> 1) * 8;
                    int bch  = 2 * ks + (q & 1);
                    uint32_t bd = buf + (2 + bl) * TILEB + brow * 128 +
                                  ((bch ^ (brow & 7)) * 16);
                    uint32_t b0, b1, b2, b3;
                    ldsm4(b0, b1, b2, b3, bd);
#pragma unroll
                    for (int al = 0; al < 2; al++)
#pragma unroll
                        for (int mt = 0; mt < 2; mt++) {
                            mma16816(acc[mt][nt * 2],     a[al][mt], b0, b1);
                            mma16816(acc[mt][nt * 2 + 1], a[al][mt], b2, b3);
                        }
                }
            }
        }
        __syncthreads();
    }

    // ---- epilogue: undo weight pre-scale, write fp32 to g_y
#pragma unroll
    for (int mt = 0; mt < 2; mt++) {
#pragma unroll
        for (int j = 0; j < 8; j++) {
            int row = bm + wm * 32 + mt * 16 + (lane >> 2);
            int col = bn + wn * 64 + j * 8 + (lane & 3) * 2;
            float2 v0, v1;
            v0.x = acc[mt][j][0] * WINV; v0.y = acc[mt][j][1] * WINV;
            v1.x = acc[mt][j][2] * WINV; v1.y = acc[mt][j][3] * WINV;
            *(float2*)&g_y[(long long)row * DIM + col] = v0;
            *(float2*)&g_y[(long long)(row + 8) * DIM + col] = v1;
        }
    }
}

// ------------- block reduction helper (128 threads) -------------
__device__ __forceinline__ void reduce2_128(float& s, float& q, float* sh) {
#pragma unroll
    for (int off = 16; off; off >>= 1) {
        s += __shfl_down_sync(0xFFFFFFFFu, s, off);
        q += __shfl_down_sync(0xFFFFFFFFu, q, off);
    }
    int w = threadIdx.x >> 5;
    if ((threadIdx.x & 31) == 0) { sh[w] = s; sh[4 + w] = q; }
    __syncthreads();
    s = sh[0] + sh[1] + sh[2] + sh[3];
    q = sh[4] + sh[5] + sh[6] + sh[7];
}

// ============================================================
// bias + LN1 + ReLU: g_y -> x1 limbs (fp16 x2)
// ============================================================
__global__ __launch_bounds__(128)
void ln_relu_kernel(const float* __restrict__ g,
                    const float* __restrict__ b,
                    const float* __restrict__ cb) {
    __shared__ float sh[8];
    int row = blockIdx.x;
    int tid = threadIdx.x;
    float4 y = ((const float4*)(g_y + (long long)row * DIM))[tid];
    float4 cbv = ((const float4*)cb)[tid];
    float4 v;
    v.x = y.x + cbv.x; v.y = y.y + cbv.y; v.z = y.z + cbv.z; v.w = y.w + cbv.w;
    float s = v.x + v.y + v.z + v.w;
    float q = v.x * v.x + v.y * v.y + v.z * v.z + v.w * v.w;
    reduce2_128(s, q, sh);
    float mean = s * (1.f / DIM);
    float var  = q * (1.f / DIM) - mean * mean;
    float rstd = rsqrtf(var + LN_EPS);
    float4 gg = ((const float4*)g)[tid];
    float4 bb = ((const float4*)b)[tid];
    float ov[4];
    ov[0] = fmaxf((v.x - mean) * rstd * gg.x + bb.x, 0.f);
    ov[1] = fmaxf((v.y - mean) * rstd * gg.y + bb.y, 0.f);
    ov[2] = fmaxf((v.z - mean) * rstd * gg.z + bb.z, 0.f);
    ov[3] = fmaxf((v.w - mean) * rstd * gg.w + bb.w, 0.f);
    __half h0[4], h1[4];
#pragma unroll
    for (int j = 0; j < 4; j++) split2(ov[j], h0[j], h1[j]);
    long long pbase = ((long long)row * DIM) / 2 + tid * 2;
    __half2 t;
    t.x = h0[0]; t.y = h0[1]; ((__half2*)g_xs[0])[pbase] = t;
    t.x = h0[2]; t.y = h0[3]; ((__half2*)g_xs[0])[pbase + 1] = t;
    t.x = h1[0]; t.y = h1[1]; ((__half2*)g_xs[1])[pbase] = t;
    t.x = h1[2]; t.y = h1[3]; ((__half2*)g_xs[1])[pbase + 1] = t;
}

// ============================================================
// bias + LN2 + ReLU + linear + duration -> g_dur
// ============================================================
__global__ __launch_bounds__(128)
void ln_dur_kernel(const float* __restrict__ g,
                   const float* __restrict__ b,
                   const float* __restrict__ lw,
                   const float* __restrict__ lb,
                   const float* __restrict__ cb) {
    __shared__ float sh[8];
    int row = blockIdx.x;
    int tid = threadIdx.x;
    float4 y = ((const float4*)(g_y + (long long)row * DIM))[tid];
    float4 cbv = ((const float4*)cb)[tid];
    float4 v;
    v.x = y.x + cbv.x; v.y = y.y + cbv.y; v.z = y.z + cbv.z; v.w = y.w + cbv.w;
    float s = v.x + v.y + v.z + v.w;
    float q = v.x * v.x + v.y * v.y + v.z * v.z + v.w * v.w;
    reduce2_128(s, q, sh);
    float mean = s * (1.f / DIM);
    float var  = q * (1.f / DIM) - mean * mean;
    float rstd = rsqrtf(var + LN_EPS);
    float4 gg = ((const float4*)g)[tid];
    float4 bb = ((const float4*)b)[tid];
    float4 ww = ((const float4*)lw)[tid];
    float ox = fmaxf((v.x - mean) * rstd * gg.x + bb.x, 0.f);
    float oy = fmaxf((v.y - mean) * rstd * gg.y + bb.y, 0.f);
    float oz = fmaxf((v.z - mean) * rstd * gg.z + bb.z, 0.f);
    float ow = fmaxf((v.w - mean) * rstd * gg.w + bb.w, 0.f);
    float t = ox * ww.x + oy * ww.y + oz * ww.z + ow * ww.w;
    __syncthreads();
    float dummy = 0.f;
    reduce2_128(t, dummy, sh);
    if (tid == 0) {
        float pred = fmaxf(t + lb[0], 0.f);
        g_dur[row] = (int)floorf(pred + 0.5f);
    }
}

// ============================================================
// Inclusive cumsum of g_dur (4096 ints), single block.
// ============================================================
__global__ __launch_bounds__(1024)
void cumsum_kernel() {
    __shared__ int part[1024];
    int tid = threadIdx.x;
    int v[4];
    int s = 0;
#pragma unroll
    for (int i = 0; i < 4; i++) { v[i] = g_dur[tid * 4 + i]; s += v[i]; }
    part[tid] = s;
    __syncthreads();
    for (int off = 1; off < 1024; off <<= 1) {
        int t = 0;
        if (tid >= off) t = part[tid - off];
        __syncthreads();
        if (tid >= off) part[tid] += t;
        __syncthreads();
    }
    int run = (tid > 0) ? part[tid - 1] : 0;
#pragma unroll
    for (int i = 0; i < 4; i++) { run += v[i]; g_cum[tid * 4 + i] = run; }
}

// ============================================================
// Length regulation: one block per output frame t.
// ============================================================
__global__ __launch_bounds__(128)
void gather_kernel(const float* __restrict__ enc,
                   float* __restrict__ out,
                   float* __restrict__ pos,
                   int write_pos) {
    int t = blockIdx.x;
    int tid = threadIdx.x;
    int total = g_cum[SEQ - 1];
    float4 val = make_float4(0.f, 0.f, 0.f, 0.f);
    if (t < total) {
        int lo = 0, hi = SEQ;
        while (lo < hi) {
            int mid = (lo + hi) >> 1;
            if (g_cum[mid] <= t) lo = mid + 1; else hi = mid;
        }
        if (lo > SEQ - 1) lo = SEQ - 1;
        val = ((const float4*)(enc + (long long)lo * DIM))[tid];
    }
    ((float4*)(out + (long long)t * DIM))[tid] = val;
    if (write_pos && tid == 0) pos[t] = (float)(t + 1);
}

// ============================================================
extern "C" void kernel_launch(void* const* d_in, const int* in_sizes, int n_in,
                              void* d_out, int out_size) {
    const float* enc = (const float*)d_in[0];
    const float* c1w = (const float*)d_in[1];
    const float* c1b = (const float*)d_in[2];
    const float* g1  = (const float*)d_in[3];
    const float* b1  = (const float*)d_in[4];
    const float* c2w = (const float*)d_in[5];
    const float* c2b = (const float*)d_in[6];
    const float* g2  = (const float*)d_in[7];
    const float* b2  = (const float*)d_in[8];
    const float* lw  = (const float*)d_in[9];
    const float* lb  = (const float*)d_in[10];
    float* out = (float*)d_out;

    cudaFuncSetAttribute(conv_mma_kernel<0>,
                         cudaFuncAttributeMaxDynamicSharedMemorySize, SMEM_DYN);
    cudaFuncSetAttribute(conv_mma_kernel<1>,
                         cudaFuncAttributeMaxDynamicSharedMemorySize, SMEM_DYN);

    split_enc_kernel<<<SEQ * DIM / 1024, 256>>>(enc);
    wsplit_kernel<<<dim3(KTOT * DIM / 256, 2), 256>>>(c1w, c2w);
    conv_mma_kernel<0><<<dim3(SEQ / 128, DIM / 128), 256, SMEM_DYN>>>();
    ln_relu_kernel<<<SEQ, 128>>>(g1, b1, c1b);
    conv_mma_kernel<1><<<dim3(SEQ / 128, DIM / 128), 256, SMEM_DYN>>>();
    ln_dur_kernel<<<SEQ, 128>>>(g2, b2, lw, lb, c2b);
    cumsum_kernel<<<1, 1024>>>();

    int write_pos = (out_size >= MAXOUT * DIM + MAXOUT) ? 1 : 0;
    gather_kernel<<<MAXOUT, 128>>>(enc, out, out + (size_t)MAXOUT * DIM, write_pos);
}